// round 7
// baseline (speedup 1.0000x reference)
#include <cuda_runtime.h>

#define NG     64
#define NN     2048
#define F      128
#define H      4
#define CHUNK  64
#define SPLIT  (NN/CHUNK)     // 32 chunks per group
#define NCHUNK (NG*SPLIT)     // 2048 work units
#define TB     256
#define PST    132
#define GRID1  444            // 148 SM x 3 CTA persistent

typedef unsigned long long u64;

__device__ float g_wa[H*F];
__device__ float g_part[NCHUNK*H*PST];
__device__ int   g_work;
__device__ int   g_gcnt[NG];

__device__ __forceinline__ u64 ffma2(u64 a, u64 b, u64 c) {
    u64 d; asm("fma.rn.f32x2 %0,%1,%2,%3;" : "=l"(d) : "l"(a), "l"(b), "l"(c)); return d;
}
__device__ __forceinline__ u64 addf2(u64 a, u64 b) {
    u64 d; asm("add.rn.f32x2 %0,%1,%2;" : "=l"(d) : "l"(a), "l"(b)); return d;
}
__device__ __forceinline__ u64 dup2(float x) {
    u64 d; asm("mov.b64 %0,{%1,%1};" : "=l"(d) : "f"(x)); return d;
}
__device__ __forceinline__ float2 u2f(u64 v) {
    float2 r; asm("mov.b64 {%0,%1},%2;" : "=f"(r.x), "=f"(r.y) : "l"(v)); return r;
}
__device__ __forceinline__ unsigned smem_u32(const void* p) {
    unsigned a;
    asm("{ .reg .u64 t; cvta.to.shared.u64 t, %1; cvt.u32.u64 %0, t; }" : "=r"(a) : "l"(p));
    return a;
}

// dynamic smem layout (bytes)
#define SX0_OFF  0         // buf0: 64 rows x 32 float4, swizzled    32768
#define SX1_OFF  32768     // buf1                                   32768
#define SWA_OFF  65536     // wa[4][128]                              2048
#define PP_OFF   67584     // float4 pp[64]                           1024
#define DP_OFF   68608     // scratch: P1 dots / P2 v / epilogue      4096
#define RED_OFF  72704     // float red[8]                              32
#define BC_OFF   72736     // broadcast ints                            16
#define SV_OFF   72752     // sinv[4]                                   16
#define SMEM_SZ  72768

// ---------------------------------------------------------------------------
__global__ void __launch_bounds__(256) k0_wa(
        const float* __restrict__ W1, const float* __restrict__ a1,
        const float* __restrict__ W2, const float* __restrict__ a2,
        const float* __restrict__ W3, const float* __restrict__ a3,
        const float* __restrict__ W4, const float* __restrict__ a4) {
    const int bid = blockIdx.x, t = threadIdx.x;
    if (bid == H) {
        if (t < NG) g_gcnt[t] = 0;
        if (t == NG) g_work = 0;
        return;
    }
    const float* W = (bid == 0) ? W1 : (bid == 1) ? W2 : (bid == 2) ? W3 : W4;
    const float* A = (bid == 0) ? a1 : (bid == 1) ? a2 : (bid == 2) ? a3 : a4;
    const int lane = t & 31, w = t >> 5;
    float4 av = *reinterpret_cast<const float4*>(A + lane*4);
    #pragma unroll
    for (int o = 0; o < 16; o++) {
        int i = w*16 + o;
        float4 wv = *reinterpret_cast<const float4*>(W + i*F + lane*4);
        float d = wv.x*av.x + wv.y*av.y + wv.z*av.z + wv.w*av.w;
        #pragma unroll
        for (int off = 16; off; off >>= 1)
            d += __shfl_xor_sync(0xffffffffu, d, off);
        if (lane == 0) g_wa[bid*F + i] = d;
    }
}

// ---------------------------------------------------------------------------
__global__ void __launch_bounds__(TB) k1_main(
        const float* __restrict__ feat,
        const float* __restrict__ W1, const float* __restrict__ W2,
        const float* __restrict__ W3, const float* __restrict__ W4,
        const float* __restrict__ Wo, float* __restrict__ out) {
    extern __shared__ char smem[];
    float*      s_wa  = (float*)(smem + SWA_OFF);
    ulonglong2* s_wa2 = (ulonglong2*)(smem + SWA_OFF);
    float*      s_dpf = (float*)(smem + DP_OFF);
    float4*     s_dp  = (float4*)(smem + DP_OFF);
    ulonglong2* s_vp2 = (ulonglong2*)(smem + DP_OFF);
    float*      s_ppf = (float*)(smem + PP_OFF);
    ulonglong2* s_pp2 = (ulonglong2*)(smem + PP_OFF);
    float*      s_red = (float*)(smem + RED_OFF);
    int*        s_bc  = (int*)(smem + BC_OFF);
    float*      s_sv  = (float*)(smem + SV_OFF);

    const int t = threadIdx.x, lane = t & 31, w = t >> 5;
    const unsigned smb = smem_u32(smem);

    s_wa[t] = g_wa[t];
    s_wa[t + 256] = g_wa[t + 256];

    // async stage of one 64-row chunk into buffer b
    auto issue_chunk = [&](int c, int b) {
        const char* src = (const char*)(feat + (size_t)c * CHUNK * F);
        unsigned base = smb + (b ? SX1_OFF : SX0_OFF);
        #pragma unroll
        for (int k = 0; k < 8; k++) {
            int q = t + k*TB;
            int row = q >> 5, c4 = q & 31;
            unsigned dst = base + (unsigned)((row*32 + (c4 ^ (row & 7))) * 16);
            asm volatile("cp.async.cg.shared.global [%0],[%1],16;"
                         :: "r"(dst), "l"(src + (size_t)q*16));
        }
        asm volatile("cp.async.commit_group;");
    };

    int cur, p = 0;
    if (t == 0) s_bc[0] = atomicAdd(&g_work, 1);
    __syncthreads();
    cur = s_bc[0];
    if (cur < NCHUNK) issue_chunk(cur, 0);

    while (cur < NCHUNK) {
        if (t == 0) s_bc[0] = atomicAdd(&g_work, 1);
        __syncthreads();                      // prev compute done; s_bc visible
        const int nxt = s_bc[0];
        if (nxt < NCHUNK) {
            issue_chunk(nxt, p ^ 1);
            asm volatile("cp.async.wait_group 1;");
        } else {
            asm volatile("cp.async.wait_group 0;");
        }
        __syncthreads();                      // buf[p] fully visible to all

        float*      s_sxf = (float*)(smem + (p ? SX1_OFF : SX0_OFF));
        ulonglong2* s_sx2 = (ulonglong2*)s_sxf;
        const int grp = cur >> 5;
        float* pb = g_part + (size_t)cur * H * PST;

        // ---- P1: 4 threads per row (quarter-columns), f32x2 dots ----------
        {
            const int row = t & 63, q = t >> 6, r7 = row & 7;
            u64 d2[H] = {0ull, 0ull, 0ull, 0ull};
            #pragma unroll
            for (int jj = 0; jj < 8; jj++) {
                int j = q*8 + jj;
                ulonglong2 f = s_sx2[row*32 + (j ^ r7)];
                #pragma unroll
                for (int h = 0; h < H; h++) {
                    ulonglong2 wv = s_wa2[h*32 + j];
                    d2[h] = ffma2(f.x, wv.x, d2[h]);
                    d2[h] = ffma2(f.y, wv.y, d2[h]);
                }
            }
            float2 a0 = u2f(d2[0]), a1 = u2f(d2[1]), a2 = u2f(d2[2]), a3 = u2f(d2[3]);
            s_dp[t] = make_float4(a0.x+a0.y, a1.x+a1.y, a2.x+a2.y, a3.x+a3.y);
        }
        __syncthreads();

        // ---- combine quarters, exp, warp s-sums ---------------------------
        {
            const int row = t & 63, h = t >> 6;
            float d = s_dpf[row*4 + h] + s_dpf[(row+64)*4 + h]
                    + s_dpf[(row+128)*4 + h] + s_dpf[(row+192)*4 + h];
            float pv = __expf(d);
            s_ppf[row*4 + h] = pv;
            float sv = pv;
            #pragma unroll
            for (int off = 16; off; off >>= 1)
                sv += __shfl_xor_sync(0xffffffffu, sv, off);
            if (lane == 0) s_red[w] = sv;
        }
        __syncthreads();

        if (t < H) pb[t*PST + F] = s_red[2*t] + s_red[2*t + 1];

        // ---- P2: 2 threads per column (32 rows each), f32x2 over heads ----
        {
            const int col = t & 127, rhalf = t >> 7;
            const int cq = col >> 2, cl = col & 3;
            const int r0 = rhalf * 32;
            u64 a01a = 0ull, a23a = 0ull, a01b = 0ull, a23b = 0ull;
            #pragma unroll 8
            for (int r = 0; r < 32; r += 2) {
                int ra = r0 + r, rb = ra + 1;
                ulonglong2 pa  = s_pp2[ra];
                ulonglong2 pbv = s_pp2[rb];
                u64 xa = dup2(s_sxf[ra*F + ((cq ^ (ra & 7)) << 2) + cl]);
                u64 xb = dup2(s_sxf[rb*F + ((cq ^ (rb & 7)) << 2) + cl]);
                a01a = ffma2(pa.x,  xa, a01a);
                a23a = ffma2(pa.y,  xa, a23a);
                a01b = ffma2(pbv.x, xb, a01b);
                a23b = ffma2(pbv.y, xb, a23b);
            }
            __syncthreads();     // s_dp fully consumed before overwrite (s_vp2 aliases)
            ulonglong2 vr;
            vr.x = addf2(a01a, a01b);
            vr.y = addf2(a23a, a23b);
            s_vp2[t] = vr;
        }
        __syncthreads();

        if (t < 128) {
            ulonglong2 A = s_vp2[t], B = s_vp2[t + 128];
            float2 v01 = u2f(addf2(A.x, B.x));
            float2 v23 = u2f(addf2(A.y, B.y));
            pb[0*PST + t] = v01.x;
            pb[1*PST + t] = v01.y;
            pb[2*PST + t] = v23.x;
            pb[3*PST + t] = v23.y;
        }

        // ---- completion; last chunk of group runs epilogue ----------------
        __threadfence();
        __syncthreads();
        if (t == 0) {
            int old = atomicAdd(&g_gcnt[grp], 1);
            s_bc[1] = (old == SPLIT - 1);
        }
        __syncthreads();
        if (s_bc[1]) {
            __threadfence();
            float* pooled = s_dpf;           // [512]  (DP scratch, not buffers!)
            float* multi  = s_dpf + 512;     // [512]
            const float* pg = g_part + (size_t)grp * SPLIT * H * PST;
            if (t < H) {
                float ss = 0.f;
                #pragma unroll
                for (int cc = 0; cc < SPLIT; cc++) ss += pg[(cc*H + t)*PST + F];
                s_sv[t] = 1.0f / ss;
            }
            __syncthreads();
            #pragma unroll
            for (int rep = 0; rep < 2; rep++) {
                int o = t + rep*256, h = o >> 7, i = o & 127;
                float vv = 0.f;
                #pragma unroll
                for (int cc = 0; cc < SPLIT; cc++) vv += pg[(cc*H + h)*PST + i];
                pooled[o] = vv * s_sv[h];
            }
            __syncthreads();
            #pragma unroll
            for (int rep = 0; rep < 2; rep++) {
                int o = t + rep*256, h = o >> 7, j = o & 127;
                const float* Wp = (h == 0) ? W1 : (h == 1) ? W2 : (h == 2) ? W3 : W4;
                float acc = 0.f;
                #pragma unroll 8
                for (int i = 0; i < F; i++)
                    acc = fmaf(pooled[h*F + i], Wp[i*F + j], acc);
                multi[o] = acc;
            }
            __syncthreads();
            if (t < 64) {
                float acc = 0.f;
                #pragma unroll 8
                for (int k = 0; k < H*F; k++)
                    acc = fmaf(multi[k], Wo[k*64 + t], acc);
                out[grp*64 + t] = (acc > 0.f) ? acc : expm1f(acc);
            }
        }

        cur = nxt;
        p ^= 1;
    }
}

// ---------------------------------------------------------------------------
extern "C" void kernel_launch(void* const* d_in, const int* in_sizes, int n_in,
                              void* d_out, int out_size) {
    const float* feat = (const float*)d_in[0];
    const float* W1   = (const float*)d_in[1];
    const float* a1   = (const float*)d_in[2];
    const float* W2   = (const float*)d_in[3];
    const float* a2   = (const float*)d_in[4];
    const float* W3   = (const float*)d_in[5];
    const float* a3   = (const float*)d_in[6];
    const float* W4   = (const float*)d_in[7];
    const float* a4   = (const float*)d_in[8];
    const float* Wo   = (const float*)d_in[9];
    float* out = (float*)d_out;

    cudaFuncSetAttribute(k1_main, cudaFuncAttributeMaxDynamicSharedMemorySize, SMEM_SZ);
    k0_wa<<<H + 1, 256>>>(W1, a1, W2, a2, W3, a3, W4, a4);
    k1_main<<<GRID1, TB, SMEM_SZ>>>(feat, W1, W2, W3, W4, Wo, out);
}

// round 8
// speedup vs baseline: 1.2798x; 1.2798x over previous
#include <cuda_runtime.h>

#define NG     64
#define NN     2048
#define F      128
#define H      4
#define CHUNK  128
#define SPLIT  (NN/CHUNK)     // 16
#define NCHUNK (NG*SPLIT)     // 1024
#define TB     512
#define PST    132
#define GRID1  148

typedef unsigned long long u64;

__device__ float g_wa[H*F];
__device__ float g_part[NCHUNK*H*PST];
__device__ int   g_work;
__device__ int   g_gcnt[NG];

__device__ __forceinline__ u64 ffma2(u64 a, u64 b, u64 c) {
    u64 d; asm("fma.rn.f32x2 %0,%1,%2,%3;" : "=l"(d) : "l"(a), "l"(b), "l"(c)); return d;
}
__device__ __forceinline__ u64 addf2(u64 a, u64 b) {
    u64 d; asm("add.rn.f32x2 %0,%1,%2;" : "=l"(d) : "l"(a), "l"(b)); return d;
}
__device__ __forceinline__ u64 dup2(float x) {
    u64 d; asm("mov.b64 %0,{%1,%1};" : "=l"(d) : "f"(x)); return d;
}
__device__ __forceinline__ float2 u2f(u64 v) {
    float2 r; asm("mov.b64 {%0,%1},%2;" : "=f"(r.x), "=f"(r.y) : "l"(v)); return r;
}
__device__ __forceinline__ unsigned smem_u32(const void* p) {
    unsigned a;
    asm("{ .reg .u64 t; cvta.to.shared.u64 t, %1; cvt.u32.u64 %0, t; }" : "=r"(a) : "l"(p));
    return a;
}

// smem layout (bytes): 3 ring buffers + scratch
#define SXB      65536      // one buffer: 128 rows x 32 float4, swizzled
#define SWA_OFF  196608     // wa[4][128]                         2048
#define PP_OFF   198656     // p[128][4]                          2048
#define DP_OFF   200704     // scratch 2048 floats                8192
#define RED_OFF  208896     // float red[16]                        64
#define BC_OFF   208960     // 4 ints                               16
#define SV_OFF   208976     // sinv[4]                              16
#define SMEM_SZ  208992

// ---------------------------------------------------------------------------
__global__ void __launch_bounds__(256) k0_wa(
        const float* __restrict__ W1, const float* __restrict__ a1,
        const float* __restrict__ W2, const float* __restrict__ a2,
        const float* __restrict__ W3, const float* __restrict__ a3,
        const float* __restrict__ W4, const float* __restrict__ a4) {
    const int bid = blockIdx.x, t = threadIdx.x;
    if (bid == H) {
        if (t < NG) g_gcnt[t] = 0;
        if (t == NG) g_work = 0;
        return;
    }
    const float* W = (bid == 0) ? W1 : (bid == 1) ? W2 : (bid == 2) ? W3 : W4;
    const float* A = (bid == 0) ? a1 : (bid == 1) ? a2 : (bid == 2) ? a3 : a4;
    const int lane = t & 31, w = t >> 5;
    float4 av = *reinterpret_cast<const float4*>(A + lane*4);
    #pragma unroll
    for (int o = 0; o < 16; o++) {
        int i = w*16 + o;
        float4 wv = *reinterpret_cast<const float4*>(W + i*F + lane*4);
        float d = wv.x*av.x + wv.y*av.y + wv.z*av.z + wv.w*av.w;
        #pragma unroll
        for (int off = 16; off; off >>= 1)
            d += __shfl_xor_sync(0xffffffffu, d, off);
        if (lane == 0) g_wa[bid*F + i] = d;
    }
}

// ---------------------------------------------------------------------------
__global__ void __launch_bounds__(TB) k1_main(
        const float* __restrict__ feat,
        const float* __restrict__ W1, const float* __restrict__ W2,
        const float* __restrict__ W3, const float* __restrict__ W4,
        const float* __restrict__ Wo, float* __restrict__ out) {
    extern __shared__ char smem[];
    float*      s_wa  = (float*)(smem + SWA_OFF);
    ulonglong2* s_wa2 = (ulonglong2*)(smem + SWA_OFF);
    float*      s_ppf = (float*)(smem + PP_OFF);
    ulonglong2* s_pp2 = (ulonglong2*)(smem + PP_OFF);
    float*      s_dpf = (float*)(smem + DP_OFF);
    float4*     s_dp  = (float4*)(smem + DP_OFF);
    ulonglong2* s_vp2 = (ulonglong2*)(smem + DP_OFF);
    float*      s_red = (float*)(smem + RED_OFF);
    int*        s_bc  = (int*)(smem + BC_OFF);
    float*      s_sv  = (float*)(smem + SV_OFF);

    const int t = threadIdx.x, lane = t & 31, w = t >> 5;
    const unsigned smb = smem_u32(smem);

    if (t < 512) s_wa[t] = g_wa[t];

    // prefetch chunk c into ring buffer b; ALWAYS commits a group (empty ok)
    auto prefetch = [&](int c, int b) {
        if (c < NCHUNK) {
            const char* src = (const char*)(feat + (size_t)c * CHUNK * F);
            unsigned base = smb + (unsigned)b * SXB;
            #pragma unroll
            for (int k = 0; k < 8; k++) {
                int q = t + k*TB;
                int row = q >> 5, c4 = q & 31;
                unsigned dst = base + (unsigned)((row*32 + (c4 ^ (row & 7))) * 16);
                asm volatile("cp.async.cg.shared.global [%0],[%1],16;"
                             :: "r"(dst), "l"(src + (size_t)q*16));
            }
        }
        asm volatile("cp.async.commit_group;");
    };

    // prime: steal 2, prefetch into buffers 0,1
    if (t == 0) s_bc[0] = atomicAdd(&g_work, 1);
    __syncthreads();
    int cur = s_bc[0];
    prefetch(cur, 0);
    if (t == 0) s_bc[1] = atomicAdd(&g_work, 1);
    __syncthreads();
    int nx = s_bc[1];
    prefetch(nx, 1);

    int buf = 0;
    while (cur < NCHUNK) {
        // steal 2-ahead, prefetch into buffer (buf+2)%3
        const int b2 = (buf == 0) ? 2 : (buf == 1) ? 0 : 1;
        if (t == 0) s_bc[b2] = atomicAdd(&g_work, 1);
        __syncthreads();                       // also: prev compute fully done
        const int c2 = s_bc[b2];
        prefetch(c2, b2);
        asm volatile("cp.async.wait_group 2;");  // cur's copy complete
        __syncthreads();

        float*      s_sxf = (float*)(smem + (unsigned)buf * SXB);
        ulonglong2* s_sx2 = (ulonglong2*)s_sxf;
        const int grp = cur >> 4;
        float* pb = g_part + (size_t)cur * H * PST;

        // ---- P1: 4 threads per row (quarter-columns), f32x2 dots ----------
        {
            const int row = t & 127, q = t >> 7, r7 = row & 7;
            u64 d2[H] = {0ull, 0ull, 0ull, 0ull};
            #pragma unroll
            for (int jj = 0; jj < 8; jj++) {
                int j = q*8 + jj;
                ulonglong2 f = s_sx2[row*32 + (j ^ r7)];
                #pragma unroll
                for (int h = 0; h < H; h++) {
                    ulonglong2 wv = s_wa2[h*32 + j];
                    d2[h] = ffma2(f.x, wv.x, d2[h]);
                    d2[h] = ffma2(f.y, wv.y, d2[h]);
                }
            }
            float2 a0 = u2f(d2[0]), a1 = u2f(d2[1]), a2 = u2f(d2[2]), a3 = u2f(d2[3]);
            s_dp[t] = make_float4(a0.x+a0.y, a1.x+a1.y, a2.x+a2.y, a3.x+a3.y);
        }
        __syncthreads();

        // ---- combine quarters, exp (1 per (row,head)), warp s-sums --------
        {
            const int row = t & 127, h = t >> 7;
            float d = s_dpf[row*4 + h] + s_dpf[(row+128)*4 + h]
                    + s_dpf[(row+256)*4 + h] + s_dpf[(row+384)*4 + h];
            float pv = __expf(d);
            s_ppf[row*4 + h] = pv;
            float sv = pv;
            #pragma unroll
            for (int off = 16; off; off >>= 1)
                sv += __shfl_xor_sync(0xffffffffu, sv, off);
            if (lane == 0) s_red[w] = sv;   // warp w: head w>>2
        }
        __syncthreads();

        if (t < H)
            pb[t*PST + F] = s_red[4*t] + s_red[4*t+1] + s_red[4*t+2] + s_red[4*t+3];

        // ---- P2: 4 threads per column (32 rows each), f32x2 over heads ----
        {
            const int col = t & 127, rq = t >> 7;
            const int cq = col >> 2, cl = col & 3;
            const int r0 = rq * 32;
            u64 a01a = 0ull, a23a = 0ull, a01b = 0ull, a23b = 0ull;
            #pragma unroll 8
            for (int r = 0; r < 32; r += 2) {
                int ra = r0 + r, rb = ra + 1;
                ulonglong2 pa  = s_pp2[ra];
                ulonglong2 pbv = s_pp2[rb];
                u64 xa = dup2(s_sxf[ra*F + ((cq ^ (ra & 7)) << 2) + cl]);
                u64 xb = dup2(s_sxf[rb*F + ((cq ^ (rb & 7)) << 2) + cl]);
                a01a = ffma2(pa.x,  xa, a01a);
                a23a = ffma2(pa.y,  xa, a23a);
                a01b = ffma2(pbv.x, xb, a01b);
                a23b = ffma2(pbv.y, xb, a23b);
            }
            __syncthreads();          // all s_dp reads done before overwrite
            ulonglong2 vr;
            vr.x = addf2(a01a, a01b);
            vr.y = addf2(a23a, a23b);
            s_vp2[t] = vr;
        }
        __syncthreads();

        if (t < 128) {
            ulonglong2 A = s_vp2[t], B = s_vp2[t+128];
            ulonglong2 C = s_vp2[t+256], D = s_vp2[t+384];
            float2 v01 = u2f(addf2(addf2(A.x, B.x), addf2(C.x, D.x)));
            float2 v23 = u2f(addf2(addf2(A.y, B.y), addf2(C.y, D.y)));
            pb[0*PST + t] = v01.x;
            pb[1*PST + t] = v01.y;
            pb[2*PST + t] = v23.x;
            pb[3*PST + t] = v23.y;
        }

        // ---- completion; last chunk of group runs epilogue ----------------
        __threadfence();
        __syncthreads();
        if (t == 0) {
            int old = atomicAdd(&g_gcnt[grp], 1);
            s_bc[3] = (old == SPLIT - 1);
        }
        __syncthreads();
        if (s_bc[3]) {
            __threadfence();
            float* pooled = s_dpf;           // [512]
            float* multi  = s_dpf + 512;     // [512]
            float* red8   = s_dpf + 1024;    // [512]
            const float* pg = g_part + (size_t)grp * SPLIT * H * PST;
            if (t < H) {
                float ss = 0.f;
                #pragma unroll
                for (int cc = 0; cc < SPLIT; cc++) ss += pg[(cc*H + t)*PST + F];
                s_sv[t] = 1.0f / ss;
            }
            __syncthreads();
            {
                int h = t >> 7, i = t & 127;
                float vv = 0.f;
                #pragma unroll
                for (int cc = 0; cc < SPLIT; cc++) vv += pg[(cc*H + h)*PST + i];
                pooled[t] = vv * s_sv[h];
            }
            __syncthreads();
            {
                int h = t >> 7, j = t & 127;
                const float* Wp = (h == 0) ? W1 : (h == 1) ? W2 : (h == 2) ? W3 : W4;
                float acc = 0.f;
                #pragma unroll 8
                for (int i = 0; i < F; i++)
                    acc = fmaf(pooled[h*F + i], Wp[i*F + j], acc);
                multi[t] = acc;
            }
            __syncthreads();
            {
                int oc = t & 63, seg = t >> 6;   // 8 segments of 64 k
                float acc = 0.f;
                #pragma unroll 8
                for (int kk = 0; kk < 64; kk++) {
                    int k = seg*64 + kk;
                    acc = fmaf(multi[k], Wo[k*64 + oc], acc);
                }
                red8[seg*64 + oc] = acc;
            }
            __syncthreads();
            if (t < 64) {
                float a = 0.f;
                #pragma unroll
                for (int sgg = 0; sgg < 8; sgg++) a += red8[sgg*64 + t];
                out[grp*64 + t] = (a > 0.f) ? a : expm1f(a);
            }
        }

        cur = nx; nx = c2; buf = (buf == 2) ? 0 : buf + 1;
    }
    asm volatile("cp.async.wait_group 0;");
}

// ---------------------------------------------------------------------------
extern "C" void kernel_launch(void* const* d_in, const int* in_sizes, int n_in,
                              void* d_out, int out_size) {
    const float* feat = (const float*)d_in[0];
    const float* W1   = (const float*)d_in[1];
    const float* a1   = (const float*)d_in[2];
    const float* W2   = (const float*)d_in[3];
    const float* a2   = (const float*)d_in[4];
    const float* W3   = (const float*)d_in[5];
    const float* a3   = (const float*)d_in[6];
    const float* W4   = (const float*)d_in[7];
    const float* a4   = (const float*)d_in[8];
    const float* Wo   = (const float*)d_in[9];
    float* out = (float*)d_out;

    cudaFuncSetAttribute(k1_main, cudaFuncAttributeMaxDynamicSharedMemorySize, SMEM_SZ);
    k0_wa<<<H + 1, 256>>>(W1, a1, W2, a2, W3, a3, W4, a4);
    k1_main<<<GRID1, TB, SMEM_SZ>>>(feat, W1, W2, W3, W4, Wo, out);
}